// round 8
// baseline (speedup 1.0000x reference)
#include <cuda_runtime.h>

// Correlation cost volume, max_disp=4.
// out[b, dx*9+dy, h, w] = (1/128) * sum_c x1[b,c,h,w] * x2pad[b,c,h+dx,w+dy]
// x1,x2: [8,128,128,128] f32 ; out: [8,81,128,128] f32.
//
// R8: 9 fat compute warps (warp = dxi; 2 rows x 16 lanes x 8px, 72 acc floats,
// 186-reg budget for deep ILP), 2 producer warps, mbarrier pipeline, XOR swizzle.

#define CC_C   128
#define CC_H   128
#define CC_W   128
#define CC_B   8
#define CC_D   4
#define CC_ND  9
#define CC_NOFF 81
#define CC_TH  2
#define CC_PX  8
#define CC_CCH 16
#define CC_NCHUNK (CC_C / CC_CCH)     // 8
#define CC_X2R (CC_TH + 2*CC_D)       // 10
#define CC_X2W (CC_W + 2*CC_D)        // 136
#define NSTAGE 2
#define NCW    9                      // compute warps (one per dxi)
#define NPT    64                     // producer threads (2 warps)
#define NTH    (NCW*32 + NPT)         // 352

#define X1SF (CC_CCH*CC_TH*CC_W)      // 4096 floats / stage
#define X2SF (CC_CCH*CC_X2R*CC_X2W)   // 21760 floats / stage
#define STF  (X1SF + X2SF)            // 25856 floats
#define STB  (STF * 4)                // 103424 B (multiple of 256)
#define DATAB 64
#define SMEM_BYTES (DATAB + NSTAGE * STB)   // 206912 B

#define N_X1F4 (X1SF / 4)                    // 1024
#define N_X2F4 (CC_CCH * CC_X2R * (CC_W/4))  // 5120
#define CHUNK_SRC_BYTES (CC_CCH * CC_H * CC_W * 4)

#define MB_FULL(s)  ((s) * 8)
#define MB_EMPTY(s) (16 + (s) * 8)

typedef unsigned long long u64t;

#define FMA2(acc, a, b) \
    asm("fma.rn.f32x2 %0, %1, %2, %0;" : "+l"(acc) : "l"(a), "l"(b))
#define PACK2(d, lo, hi) \
    asm("mov.b64 %0, {%1, %2};" : "=l"(d) : "f"(lo), "f"(hi))
#define UNPACK2(lo, hi, v) \
    asm("mov.b64 {%0, %1}, %2;" : "=f"(lo), "=f"(hi) : "l"(v))

__device__ __forceinline__ void cp16(unsigned dst, const void* src, int src_bytes) {
    asm volatile("cp.async.cg.shared.global [%0], [%1], 16, %2;\n"
                 :: "r"(dst), "l"(src), "r"(src_bytes));
}
// 16B XOR swizzle: decollides 32B-stride LDS.128 phases (verified both warp halves).
__device__ __forceinline__ unsigned swz(unsigned a) { return a ^ ((a >> 3) & 0x10u); }

__device__ __forceinline__ void mbar_init(unsigned addr, unsigned cnt) {
    asm volatile("mbarrier.init.shared.b64 [%0], %1;" :: "r"(addr), "r"(cnt) : "memory");
}
__device__ __forceinline__ void mbar_arrive(unsigned addr) {
    asm volatile("mbarrier.arrive.shared.b64 _, [%0];" :: "r"(addr) : "memory");
}
__device__ __forceinline__ void cpasync_arrive_noinc(unsigned addr) {
    asm volatile("cp.async.mbarrier.arrive.noinc.shared::cta.b64 [%0];"
                 :: "r"(addr) : "memory");
}
__device__ __forceinline__ void mbar_wait_acq(unsigned addr, unsigned parity) {
    asm volatile(
        "{\n\t.reg .pred P;\n\t"
        "WL_%=:\n\t"
        "mbarrier.try_wait.parity.acquire.cta.shared::cta.b64 P, [%0], %1, 0x989680;\n\t"
        "@P bra.uni WD_%=;\n\tbra.uni WL_%=;\n\tWD_%=:\n\t}"
        :: "r"(addr), "r"(parity) : "memory");
}
__device__ __forceinline__ void mbar_wait_rlx(unsigned addr, unsigned parity) {
    asm volatile(
        "{\n\t.reg .pred P;\n\t"
        "WL_%=:\n\t"
        "mbarrier.try_wait.parity.relaxed.cta.shared::cta.b64 P, [%0], %1, 0x989680;\n\t"
        "@P bra.uni WD_%=;\n\tbra.uni WL_%=;\n\tWD_%=:\n\t}"
        :: "r"(addr), "r"(parity) : "memory");
}

__device__ __forceinline__ void producer_fill(unsigned smem_u32, unsigned stoff,
                                              const char* bx1, const char* bx2,
                                              unsigned coff, int ptid, int h0)
{
#pragma unroll 4
    for (int i = ptid; i < N_X1F4; i += NPT) {
        const int c = i >> 6, rem = i & 63, hh = rem >> 5, q = rem & 31;
        const unsigned rel = (unsigned)((c * CC_TH + hh) * CC_W + 4 * q) * 4u;
        cp16(smem_u32 + stoff + swz(rel),
             bx1 + ((size_t)(c * CC_H + h0 + hh) * CC_W + 4 * q) * 4 + coff, 16);
    }
#pragma unroll 4
    for (int j = ptid; j < N_X2F4; j += NPT) {
        const int c = j / (CC_X2R * 32);
        const int rem = j - c * (CC_X2R * 32);
        const int r = rem >> 5, q = rem & 31;
        const int grow = h0 - CC_D + r;
        const int ok = (grow >= 0) && (grow < CC_H);
        const unsigned rel =
            (unsigned)(X1SF + (c * CC_X2R + r) * CC_X2W + CC_D + 4 * q) * 4u;
        cp16(smem_u32 + stoff + swz(rel),
             bx2 + ((size_t)(c * CC_H + (ok ? grow : 0)) * CC_W + 4 * q) * 4 + coff,
             ok ? 16 : 0);
    }
}

extern "C" __global__ void __launch_bounds__(NTH, 1)
corr_kernel(const float* __restrict__ x1,
            const float* __restrict__ x2,
            float* __restrict__ out)
{
    extern __shared__ char smem_c[];
    const int tid = threadIdx.x;
    const int b   = blockIdx.y;
    const int h0  = blockIdx.x * CC_TH;

    unsigned smem_u32;
    asm("{ .reg .u64 t; cvta.to.shared.u64 t, %1; cvt.u32.u64 %0, t; }"
        : "=r"(smem_u32) : "l"(smem_c));

    if (tid == 0) {
        mbar_init(smem_u32 + MB_FULL(0), NPT);
        mbar_init(smem_u32 + MB_FULL(1), NPT);
        mbar_init(smem_u32 + MB_EMPTY(0), NCW * 32);
        mbar_init(smem_u32 + MB_EMPTY(1), NCW * 32);
    }

    // ---- zero left/right x2 pads once per stage (swizzled like fills) ----
    for (int i = tid; i < NSTAGE * CC_CCH * CC_X2R * 2; i += NTH) {
        const int s = i / (CC_CCH * CC_X2R * 2);
        const int rem = i % (CC_CCH * CC_X2R * 2);
        const int cr = rem >> 1, side = rem & 1;
        const unsigned rel =
            (unsigned)(X1SF + cr * CC_X2W + (side ? (CC_D + CC_W) : 0)) * 4u;
        *(float4*)(smem_c + DATAB + s * STB + swz(rel)) = make_float4(0.f, 0.f, 0.f, 0.f);
    }
    __syncthreads();

    const char* bx1 = (const char*)(x1 + (size_t)b * CC_C * CC_H * CC_W);
    const char* bx2 = (const char*)(x2 + (size_t)b * CC_C * CC_H * CC_W);

    if (tid >= NCW * 32) {
        // ================= PRODUCER (2 warps) =================
        const int ptid = tid - NCW * 32;
        unsigned eph0 = 1, eph1 = 1;
        for (int fc = 0; fc < CC_NCHUNK; ++fc) {
            const int s = fc & 1;
            if (s) { mbar_wait_rlx(smem_u32 + MB_EMPTY(1), eph1); eph1 ^= 1; }
            else   { mbar_wait_rlx(smem_u32 + MB_EMPTY(0), eph0); eph0 ^= 1; }
            producer_fill(smem_u32, DATAB + (unsigned)s * STB, bx1, bx2,
                          (unsigned)fc * CHUNK_SRC_BYTES, ptid, h0);
            cpasync_arrive_noinc(smem_u32 + MB_FULL(s));
        }
        return;
    }

    // ================= CONSUMER (9 warps, warp = dxi) =================
    const int warp = tid >> 5;        // dxi 0..8
    const int lane = tid & 31;
    const int hl   = lane >> 4;       // 0..1 local row
    const int wg   = lane & 15;       // 8px group
    const int dxi  = warp;

    const unsigned x1rel0 = (unsigned)(hl * CC_W + CC_PX * wg) * 4u;
    const unsigned x2rel0 = (unsigned)(X1SF + (hl + dxi) * CC_X2W + CC_PX * wg) * 4u;

    u64t acc2[CC_ND][4] = {};   // 9 dy x 4 pixel-pairs (packed f32x2)
    unsigned fph0 = 0, fph1 = 0;

    for (int chunk = 0; chunk < CC_NCHUNK; ++chunk) {
        const int s = chunk & 1;
        if (s) { mbar_wait_acq(smem_u32 + MB_FULL(1), fph1); fph1 ^= 1; }
        else   { mbar_wait_acq(smem_u32 + MB_FULL(0), fph0); fph0 ^= 1; }

        const char* stc = smem_c + DATAB + s * STB;

#pragma unroll
        for (int c = 0; c < CC_CCH; ++c) {
            union { float4 f4[2]; float sv[8];  u64t u[4]; } A;
            union { float4 f4[4]; float sv[16]; u64t u[8]; } V;
            const unsigned x1r = x1rel0 + (unsigned)(c * CC_TH * CC_W) * 4u;
            const unsigned x2r = x2rel0 + (unsigned)(c * CC_X2R * CC_X2W) * 4u;
            A.f4[0] = *(const float4*)(stc + swz(x1r));
            A.f4[1] = *(const float4*)(stc + swz(x1r + 16u));
            V.f4[0] = *(const float4*)(stc + swz(x2r));
            V.f4[1] = *(const float4*)(stc + swz(x2r + 16u));
            V.f4[2] = *(const float4*)(stc + swz(x2r + 32u));
            V.f4[3] = *(const float4*)(stc + swz(x2r + 48u));

            u64t o[7];   // odd-parity window pairs
#pragma unroll
            for (int m = 0; m < 7; ++m)
                PACK2(o[m], V.sv[2 * m + 1], V.sv[2 * m + 2]);

#pragma unroll
            for (int t = 0; t < 5; ++t)       // even dy = 2t
#pragma unroll
                for (int j = 0; j < 4; ++j)
                    FMA2(acc2[2 * t][j], A.u[j], V.u[t + j]);
#pragma unroll
            for (int t = 0; t < 4; ++t)       // odd dy = 2t+1
#pragma unroll
                for (int j = 0; j < 4; ++j)
                    FMA2(acc2[2 * t + 1][j], A.u[j], o[t + j]);
        }
        if (s) mbar_arrive(smem_u32 + MB_EMPTY(1));
        else   mbar_arrive(smem_u32 + MB_EMPTY(0));
    }

    // ---- epilogue: scale by 1/C, store 9 x 2 float4 per thread ----
    const float inv = 1.0f / (float)CC_C;
    const int h = h0 + hl;
#pragma unroll
    for (int dy = 0; dy < CC_ND; ++dy) {
        float f[8];
#pragma unroll
        for (int j = 0; j < 4; ++j)
            UNPACK2(f[2 * j], f[2 * j + 1], acc2[dy][j]);
        float4 r0, r1;
        r0.x = f[0] * inv; r0.y = f[1] * inv; r0.z = f[2] * inv; r0.w = f[3] * inv;
        r1.x = f[4] * inv; r1.y = f[5] * inv; r1.z = f[6] * inv; r1.w = f[7] * inv;
        float* op = &out[(((size_t)(b * CC_NOFF + dxi * CC_ND + dy) * CC_H) + h) * CC_W
                         + CC_PX * wg];
        ((float4*)op)[0] = r0;
        ((float4*)op)[1] = r1;
    }
}

extern "C" void kernel_launch(void* const* d_in, const int* in_sizes, int n_in,
                              void* d_out, int out_size)
{
    const float* x1 = (const float*)d_in[0];
    const float* x2 = (const float*)d_in[1];
    float* out = (float*)d_out;

    cudaFuncSetAttribute(corr_kernel,
                         cudaFuncAttributeMaxDynamicSharedMemorySize, SMEM_BYTES);
    dim3 grid(CC_H / CC_TH, CC_B);   // (64, 8) = 512 blocks
    corr_kernel<<<grid, NTH, SMEM_BYTES>>>(x1, x2, out);
}

// round 9
// speedup vs baseline: 1.0868x; 1.0868x over previous
#include <cuda_runtime.h>

// Correlation cost volume, max_disp=4.
// out[b, dx*9+dy, h, w] = (1/128) * sum_c x1[b,c,h,w] * x2pad[b,c,h+dx,w+dy]
// x1,x2: [8,128,128,128] f32 ; out: [8,81,128,128] f32.
//
// R9: R8 (9 fat warps x 8px + 2 producer warps, mbarrier pipe, XOR swizzle)
//     + CCH=8/NSTAGE=3 (deeper pipeline, finer chunks)
//     + 128-aligned x2 row stride (640B) so swizzled bases hoist out of the
//       channel loop -> inner LDS use immediate offsets, near-zero address ALU.

#define CC_C   128
#define CC_H   128
#define CC_W   128
#define CC_B   8
#define CC_D   4
#define CC_ND  9
#define CC_NOFF 81
#define CC_TH  2
#define CC_PX  8
#define CC_CCH 8
#define CC_NCHUNK (CC_C / CC_CCH)     // 16
#define CC_X2R (CC_TH + 2*CC_D)       // 10
#define CC_X2WP 160                   // padded row: 640 B = 5*128 (data in [4,132))
#define NSTAGE 3
#define NCW    9
#define NPT    64
#define NTH    (NCW*32 + NPT)         // 352

#define X1B   (CC_CCH*CC_TH*CC_W*4)        // 8192 B x1 region / stage
#define X2B   (CC_CCH*CC_X2R*CC_X2WP*4)    // 51200 B x2 region / stage
#define STB   (X1B + X2B)                  // 59392 B / stage (mult of 128)
#define DATAB 64
#define SMEM_BYTES (DATAB + NSTAGE * STB)  // 178240 B

#define N_X1F4 (X1B/16)                    // 512
#define N_X2F4 (CC_CCH*CC_X2R*(CC_W/4))    // 2560
#define CHUNK_SRC_BYTES (CC_CCH*CC_H*CC_W*4)

#define MB_FULL(s)  ((s) * 8)
#define MB_EMPTY(s) (32 + (s) * 8)

typedef unsigned long long u64t;

#define FMA2(acc, a, b) \
    asm("fma.rn.f32x2 %0, %1, %2, %0;" : "+l"(acc) : "l"(a), "l"(b))
#define PACK2(d, lo, hi) \
    asm("mov.b64 %0, {%1, %2};" : "=l"(d) : "f"(lo), "f"(hi))
#define UNPACK2(lo, hi, v) \
    asm("mov.b64 {%0, %1}, %2;" : "=f"(lo), "=f"(hi) : "l"(v))

__device__ __forceinline__ void cp16(unsigned dst, const void* src, int src_bytes) {
    asm volatile("cp.async.cg.shared.global [%0], [%1], 16, %2;\n"
                 :: "r"(dst), "l"(src), "r"(src_bytes));
}
// 16B XOR swizzle (bank decollision for 32B lane stride). Mask depends only on bit7.
__device__ __forceinline__ unsigned swz(unsigned a) { return a ^ ((a >> 3) & 0x10u); }

__device__ __forceinline__ void mbar_init(unsigned addr, unsigned cnt) {
    asm volatile("mbarrier.init.shared.b64 [%0], %1;" :: "r"(addr), "r"(cnt) : "memory");
}
__device__ __forceinline__ void mbar_arrive(unsigned addr) {
    asm volatile("mbarrier.arrive.shared.b64 _, [%0];" :: "r"(addr) : "memory");
}
__device__ __forceinline__ void cpasync_arrive_noinc(unsigned addr) {
    asm volatile("cp.async.mbarrier.arrive.noinc.shared::cta.b64 [%0];"
                 :: "r"(addr) : "memory");
}
__device__ __forceinline__ void mbar_wait_acq(unsigned addr, unsigned parity) {
    asm volatile(
        "{\n\t.reg .pred P;\n\t"
        "WL_%=:\n\t"
        "mbarrier.try_wait.parity.acquire.cta.shared::cta.b64 P, [%0], %1, 0x989680;\n\t"
        "@P bra.uni WD_%=;\n\tbra.uni WL_%=;\n\tWD_%=:\n\t}"
        :: "r"(addr), "r"(parity) : "memory");
}
__device__ __forceinline__ void mbar_wait_rlx(unsigned addr, unsigned parity) {
    asm volatile(
        "{\n\t.reg .pred P;\n\t"
        "WL_%=:\n\t"
        "mbarrier.try_wait.parity.relaxed.cta.shared::cta.b64 P, [%0], %1, 0x989680;\n\t"
        "@P bra.uni WD_%=;\n\tbra.uni WL_%=;\n\tWD_%=:\n\t}"
        :: "r"(addr), "r"(parity) : "memory");
}

__device__ __forceinline__ void producer_fill(unsigned smem_u32, unsigned stoff,
                                              const char* bx1, const char* bx2,
                                              unsigned coff, int ptid, int h0)
{
    // x1: 512 items (8/thread). layout: rowstride 512B, chanstride 1024B.
#pragma unroll
    for (int k = 0; k < N_X1F4 / NPT; ++k) {
        const int i = ptid + k * NPT;
        const int c = i >> 6, rem = i & 63, hh = rem >> 5, q = rem & 31;
        const unsigned rel = (unsigned)((c * CC_TH + hh) * CC_W + 4 * q) * 4u;
        cp16(smem_u32 + stoff + swz(rel),
             bx1 + ((size_t)(c * CC_H + h0 + hh) * CC_W + 4 * q) * 4 + coff, 16);
    }
    // x2: 2560 items (40/thread). padded rows 640B, data at [16, 528).
#pragma unroll
    for (int k = 0; k < N_X2F4 / NPT; ++k) {
        const int j = ptid + k * NPT;
        const int c = j / (CC_X2R * 32);
        const int rem = j - c * (CC_X2R * 32);
        const int r = rem >> 5, q = rem & 31;
        const int grow = h0 - CC_D + r;
        const int ok = (grow >= 0) && (grow < CC_H);
        const unsigned rel =
            (unsigned)(X1B + ((c * CC_X2R + r) * CC_X2WP + CC_D + 4 * q) * 4);
        cp16(smem_u32 + stoff + swz(rel),
             bx2 + ((size_t)(c * CC_H + (ok ? grow : 0)) * CC_W + 4 * q) * 4 + coff,
             ok ? 16 : 0);
    }
}

extern "C" __global__ void __launch_bounds__(NTH, 1)
corr_kernel(const float* __restrict__ x1,
            const float* __restrict__ x2,
            float* __restrict__ out)
{
    extern __shared__ char smem_c[];
    const int tid = threadIdx.x;
    const int b   = blockIdx.y;
    const int h0  = blockIdx.x * CC_TH;

    unsigned smem_u32;
    asm("{ .reg .u64 t; cvta.to.shared.u64 t, %1; cvt.u32.u64 %0, t; }"
        : "=r"(smem_u32) : "l"(smem_c));

    if (tid == 0) {
#pragma unroll
        for (int s = 0; s < NSTAGE; ++s) {
            mbar_init(smem_u32 + MB_FULL(s), NPT);
            mbar_init(smem_u32 + MB_EMPTY(s), NCW * 32);
        }
    }

    // ---- zero x2 pads once per stage: left [0,4) and right [132,136) floats ----
    for (int i = tid; i < NSTAGE * CC_CCH * CC_X2R * 2; i += NTH) {
        const int s = i / (CC_CCH * CC_X2R * 2);
        const int rem = i % (CC_CCH * CC_X2R * 2);
        const int cr = rem >> 1, side = rem & 1;
        const unsigned rel =
            (unsigned)(X1B + (cr * CC_X2WP + (side ? (CC_D + CC_W) : 0)) * 4);
        *(float4*)(smem_c + DATAB + s * STB + swz(rel)) = make_float4(0.f, 0.f, 0.f, 0.f);
    }
    __syncthreads();

    const char* bx1 = (const char*)(x1 + (size_t)b * CC_C * CC_H * CC_W);
    const char* bx2 = (const char*)(x2 + (size_t)b * CC_C * CC_H * CC_W);

    if (tid >= NCW * 32) {
        // ================= PRODUCER (2 warps) =================
        const int ptid = tid - NCW * 32;
        int s = 0; unsigned ph = 1;       // flipped phase: first waits pass
        for (int fc = 0; fc < CC_NCHUNK; ++fc) {
            mbar_wait_rlx(smem_u32 + MB_EMPTY(s), ph);
            producer_fill(smem_u32, DATAB + (unsigned)s * STB, bx1, bx2,
                          (unsigned)fc * CHUNK_SRC_BYTES, ptid, h0);
            cpasync_arrive_noinc(smem_u32 + MB_FULL(s));
            if (++s == NSTAGE) { s = 0; ph ^= 1; }
        }
        return;
    }

    // ================= CONSUMER (9 warps, warp = dxi) =================
    const int warp = tid >> 5;        // dxi 0..8
    const int lane = tid & 31;
    const int hl   = lane >> 4;       // 0..1 local row
    const int wg   = lane & 15;       // 8px group
    const int dxi  = warp;

    // Precomputed swizzled bases (channel strides are 128-aligned -> commute).
    const unsigned x1rel0 = (unsigned)(hl * CC_W + CC_PX * wg) * 4u;
    const unsigned x2rel0 = (unsigned)(X1B + ((hl + dxi) * CC_X2WP + CC_PX * wg) * 4);
    const unsigned sA0 = swz(x1rel0),        sA1 = swz(x1rel0 + 16u);
    const unsigned sV0 = swz(x2rel0),        sV1 = swz(x2rel0 + 16u);
    const unsigned sV2 = swz(x2rel0 + 32u),  sV3 = swz(x2rel0 + 48u);

    u64t acc2[CC_ND][4] = {};
    int s = 0; unsigned ph = 0;

    for (int chunk = 0; chunk < CC_NCHUNK; ++chunk) {
        mbar_wait_acq(smem_u32 + MB_FULL(s), ph);
        const char* stc = smem_c + DATAB + s * STB;

#pragma unroll
        for (int c = 0; c < CC_CCH; ++c) {
            union { float4 f4[2]; float sv[8];  u64t u[4]; } A;
            union { float4 f4[4]; float sv[16]; u64t u[8]; } V;
            // channel strides: x1 1024B, x2 6400B (both 128-aligned, bit4/7 clear)
            A.f4[0] = *(const float4*)(stc + sA0 + c * 1024);
            A.f4[1] = *(const float4*)(stc + sA1 + c * 1024);
            V.f4[0] = *(const float4*)(stc + sV0 + c * 6400);
            V.f4[1] = *(const float4*)(stc + sV1 + c * 6400);
            V.f4[2] = *(const float4*)(stc + sV2 + c * 6400);
            V.f4[3] = *(const float4*)(stc + sV3 + c * 6400);

            u64t o[7];
#pragma unroll
            for (int m = 0; m < 7; ++m)
                PACK2(o[m], V.sv[2 * m + 1], V.sv[2 * m + 2]);

#pragma unroll
            for (int t = 0; t < 5; ++t)       // even dy = 2t
#pragma unroll
                for (int j = 0; j < 4; ++j)
                    FMA2(acc2[2 * t][j], A.u[j], V.u[t + j]);
#pragma unroll
            for (int t = 0; t < 4; ++t)       // odd dy = 2t+1
#pragma unroll
                for (int j = 0; j < 4; ++j)
                    FMA2(acc2[2 * t + 1][j], A.u[j], o[t + j]);
        }
        mbar_arrive(smem_u32 + MB_EMPTY(s));
        if (++s == NSTAGE) { s = 0; ph ^= 1; }
    }

    // ---- epilogue: scale by 1/C, store 9 x 2 float4 per thread ----
    const float inv = 1.0f / (float)CC_C;
    const int h = h0 + hl;
#pragma unroll
    for (int dy = 0; dy < CC_ND; ++dy) {
        float f[8];
#pragma unroll
        for (int j = 0; j < 4; ++j)
            UNPACK2(f[2 * j], f[2 * j + 1], acc2[dy][j]);
        float4 r0, r1;
        r0.x = f[0] * inv; r0.y = f[1] * inv; r0.z = f[2] * inv; r0.w = f[3] * inv;
        r1.x = f[4] * inv; r1.y = f[5] * inv; r1.z = f[6] * inv; r1.w = f[7] * inv;
        float* op = &out[(((size_t)(b * CC_NOFF + dxi * CC_ND + dy) * CC_H) + h) * CC_W
                         + CC_PX * wg];
        ((float4*)op)[0] = r0;
        ((float4*)op)[1] = r1;
    }
}

extern "C" void kernel_launch(void* const* d_in, const int* in_sizes, int n_in,
                              void* d_out, int out_size)
{
    const float* x1 = (const float*)d_in[0];
    const float* x2 = (const float*)d_in[1];
    float* out = (float*)d_out;

    cudaFuncSetAttribute(corr_kernel,
                         cudaFuncAttributeMaxDynamicSharedMemorySize, SMEM_BYTES);
    dim3 grid(CC_H / CC_TH, CC_B);   // (64, 8) = 512 blocks
    corr_kernel<<<grid, NTH, SMEM_BYTES>>>(x1, x2, out);
}

// round 10
// speedup vs baseline: 1.1918x; 1.0966x over previous
#include <cuda_runtime.h>

// Correlation cost volume, max_disp=4.
// out[b, dx*9+dy, h, w] = (1/128) * sum_c x1[b,c,h,w] * x2pad[b,c,h+dx,w+dy]
// x1,x2: [8,128,128,128] f32 ; out: [8,81,128,128] f32.
//
// R10: persistent blocks (grid=148), mbarrier pipeline runs continuously across
// tiles (producer prefetches next tile while consumer drains current); elected
// per-warp empty-arrives. Compute core identical to R9 (9 fat warps x 8px,
// immediate-offset swizzled LDS, packed f32x2).

#define CC_C   128
#define CC_H   128
#define CC_W   128
#define CC_B   8
#define CC_D   4
#define CC_ND  9
#define CC_NOFF 81
#define CC_TH  2
#define CC_PX  8
#define CC_CCH 8
#define CC_NCHUNK (CC_C / CC_CCH)     // 16
#define CC_X2R (CC_TH + 2*CC_D)       // 10
#define CC_X2WP 160                   // padded row: 640 B (data floats [4,132))
#define NSTAGE 3
#define NCW    9
#define NPT    64
#define NTH    (NCW*32 + NPT)         // 352
#define NBLK   148
#define NTILES (CC_B * (CC_H / CC_TH))  // 512

#define X1B   (CC_CCH*CC_TH*CC_W*4)        // 8192 B / stage
#define X2B   (CC_CCH*CC_X2R*CC_X2WP*4)    // 51200 B / stage
#define STB   (X1B + X2B)                  // 59392 B / stage
#define DATAB 64
#define SMEM_BYTES (DATAB + NSTAGE * STB)  // 178240 B

#define N_X1F4 (X1B/16)                    // 512
#define N_X2F4 (CC_CCH*CC_X2R*(CC_W/4))    // 2560
#define CHUNK_SRC_BYTES (CC_CCH*CC_H*CC_W*4)

#define MB_FULL(s)  ((s) * 8)
#define MB_EMPTY(s) (32 + (s) * 8)

typedef unsigned long long u64t;

#define FMA2(acc, a, b) \
    asm("fma.rn.f32x2 %0, %1, %2, %0;" : "+l"(acc) : "l"(a), "l"(b))
#define PACK2(d, lo, hi) \
    asm("mov.b64 %0, {%1, %2};" : "=l"(d) : "f"(lo), "f"(hi))
#define UNPACK2(lo, hi, v) \
    asm("mov.b64 {%0, %1}, %2;" : "=f"(lo), "=f"(hi) : "l"(v))

__device__ __forceinline__ void cp16(unsigned dst, const void* src, int src_bytes) {
    asm volatile("cp.async.cg.shared.global [%0], [%1], 16, %2;\n"
                 :: "r"(dst), "l"(src), "r"(src_bytes));
}
__device__ __forceinline__ unsigned swz(unsigned a) { return a ^ ((a >> 3) & 0x10u); }

__device__ __forceinline__ void mbar_init(unsigned addr, unsigned cnt) {
    asm volatile("mbarrier.init.shared.b64 [%0], %1;" :: "r"(addr), "r"(cnt) : "memory");
}
__device__ __forceinline__ void mbar_arrive(unsigned addr) {
    asm volatile("mbarrier.arrive.shared.b64 _, [%0];" :: "r"(addr) : "memory");
}
__device__ __forceinline__ void cpasync_arrive_noinc(unsigned addr) {
    asm volatile("cp.async.mbarrier.arrive.noinc.shared::cta.b64 [%0];"
                 :: "r"(addr) : "memory");
}
__device__ __forceinline__ void mbar_wait_acq(unsigned addr, unsigned parity) {
    asm volatile(
        "{\n\t.reg .pred P;\n\t"
        "WL_%=:\n\t"
        "mbarrier.try_wait.parity.acquire.cta.shared::cta.b64 P, [%0], %1, 0x989680;\n\t"
        "@P bra.uni WD_%=;\n\tbra.uni WL_%=;\n\tWD_%=:\n\t}"
        :: "r"(addr), "r"(parity) : "memory");
}
__device__ __forceinline__ void mbar_wait_rlx(unsigned addr, unsigned parity) {
    asm volatile(
        "{\n\t.reg .pred P;\n\t"
        "WL_%=:\n\t"
        "mbarrier.try_wait.parity.relaxed.cta.shared::cta.b64 P, [%0], %1, 0x989680;\n\t"
        "@P bra.uni WD_%=;\n\tbra.uni WL_%=;\n\tWD_%=:\n\t}"
        :: "r"(addr), "r"(parity) : "memory");
}

__device__ __forceinline__ void producer_fill(unsigned smem_u32, unsigned stoff,
                                              const char* bx1, const char* bx2,
                                              unsigned coff, int ptid, int h0)
{
#pragma unroll
    for (int k = 0; k < N_X1F4 / NPT; ++k) {
        const int i = ptid + k * NPT;
        const int c = i >> 6, rem = i & 63, hh = rem >> 5, q = rem & 31;
        const unsigned rel = (unsigned)((c * CC_TH + hh) * CC_W + 4 * q) * 4u;
        cp16(smem_u32 + stoff + swz(rel),
             bx1 + ((size_t)(c * CC_H + h0 + hh) * CC_W + 4 * q) * 4 + coff, 16);
    }
#pragma unroll
    for (int k = 0; k < N_X2F4 / NPT; ++k) {
        const int j = ptid + k * NPT;
        const int c = j / (CC_X2R * 32);
        const int rem = j - c * (CC_X2R * 32);
        const int r = rem >> 5, q = rem & 31;
        const int grow = h0 - CC_D + r;
        const int ok = (grow >= 0) && (grow < CC_H);
        const unsigned rel =
            (unsigned)(X1B + ((c * CC_X2R + r) * CC_X2WP + CC_D + 4 * q) * 4);
        cp16(smem_u32 + stoff + swz(rel),
             bx2 + ((size_t)(c * CC_H + (ok ? grow : 0)) * CC_W + 4 * q) * 4 + coff,
             ok ? 16 : 0);
    }
}

extern "C" __global__ void __launch_bounds__(NTH, 1)
corr_kernel(const float* __restrict__ x1,
            const float* __restrict__ x2,
            float* __restrict__ out)
{
    extern __shared__ char smem_c[];
    const int tid = threadIdx.x;

    unsigned smem_u32;
    asm("{ .reg .u64 t; cvta.to.shared.u64 t, %1; cvt.u32.u64 %0, t; }"
        : "=r"(smem_u32) : "l"(smem_c));

    if (tid == 0) {
#pragma unroll
        for (int s = 0; s < NSTAGE; ++s) {
            mbar_init(smem_u32 + MB_FULL(s), NPT);
            mbar_init(smem_u32 + MB_EMPTY(s), NCW);   // elected per-warp arrives
        }
    }

    // ---- zero x2 pads once per stage ----
    for (int i = tid; i < NSTAGE * CC_CCH * CC_X2R * 2; i += NTH) {
        const int s = i / (CC_CCH * CC_X2R * 2);
        const int rem = i % (CC_CCH * CC_X2R * 2);
        const int cr = rem >> 1, side = rem & 1;
        const unsigned rel =
            (unsigned)(X1B + (cr * CC_X2WP + (side ? (CC_D + CC_W) : 0)) * 4);
        *(float4*)(smem_c + DATAB + s * STB + swz(rel)) = make_float4(0.f, 0.f, 0.f, 0.f);
    }
    __syncthreads();

    if (tid >= NCW * 32) {
        // ================= PRODUCER (2 warps), persistent =================
        const int ptid = tid - NCW * 32;
        int s = 0; unsigned ph = 1;       // flipped: first NSTAGE waits pass
        for (int t = blockIdx.x; t < NTILES; t += NBLK) {
            const int b  = t >> 6;
            const int h0 = (t & 63) * CC_TH;
            const char* bx1 = (const char*)(x1 + (size_t)b * CC_C * CC_H * CC_W);
            const char* bx2 = (const char*)(x2 + (size_t)b * CC_C * CC_H * CC_W);
            for (int fc = 0; fc < CC_NCHUNK; ++fc) {
                mbar_wait_rlx(smem_u32 + MB_EMPTY(s), ph);
                producer_fill(smem_u32, DATAB + (unsigned)s * STB, bx1, bx2,
                              (unsigned)fc * CHUNK_SRC_BYTES, ptid, h0);
                cpasync_arrive_noinc(smem_u32 + MB_FULL(s));
                if (++s == NSTAGE) { s = 0; ph ^= 1; }
            }
        }
        return;
    }

    // ================= CONSUMER (9 warps, warp = dxi), persistent =================
    const int warp = tid >> 5;        // dxi 0..8
    const int lane = tid & 31;
    const int hl   = lane >> 4;       // 0..1 local row
    const int wg   = lane & 15;       // 8px group
    const int dxi  = warp;

    const unsigned x1rel0 = (unsigned)(hl * CC_W + CC_PX * wg) * 4u;
    const unsigned x2rel0 = (unsigned)(X1B + ((hl + dxi) * CC_X2WP + CC_PX * wg) * 4);
    const unsigned sA0 = swz(x1rel0),        sA1 = swz(x1rel0 + 16u);
    const unsigned sV0 = swz(x2rel0),        sV1 = swz(x2rel0 + 16u);
    const unsigned sV2 = swz(x2rel0 + 32u),  sV3 = swz(x2rel0 + 48u);
    const float inv = 1.0f / (float)CC_C;

    int s = 0; unsigned ph = 0;

    for (int t = blockIdx.x; t < NTILES; t += NBLK) {
        const int b  = t >> 6;
        const int h0 = (t & 63) * CC_TH;

        u64t acc2[CC_ND][4] = {};

        for (int chunk = 0; chunk < CC_NCHUNK; ++chunk) {
            mbar_wait_acq(smem_u32 + MB_FULL(s), ph);
            const char* stc = smem_c + DATAB + s * STB;

#pragma unroll
            for (int c = 0; c < CC_CCH; ++c) {
                union { float4 f4[2]; float sv[8];  u64t u[4]; } A;
                union { float4 f4[4]; float sv[16]; u64t u[8]; } V;
                A.f4[0] = *(const float4*)(stc + sA0 + c * 1024);
                A.f4[1] = *(const float4*)(stc + sA1 + c * 1024);
                V.f4[0] = *(const float4*)(stc + sV0 + c * 6400);
                V.f4[1] = *(const float4*)(stc + sV1 + c * 6400);
                V.f4[2] = *(const float4*)(stc + sV2 + c * 6400);
                V.f4[3] = *(const float4*)(stc + sV3 + c * 6400);

                u64t o[7];
#pragma unroll
                for (int m = 0; m < 7; ++m)
                    PACK2(o[m], V.sv[2 * m + 1], V.sv[2 * m + 2]);

#pragma unroll
                for (int tt = 0; tt < 5; ++tt)       // even dy = 2tt
#pragma unroll
                    for (int j = 0; j < 4; ++j)
                        FMA2(acc2[2 * tt][j], A.u[j], V.u[tt + j]);
#pragma unroll
                for (int tt = 0; tt < 4; ++tt)       // odd dy = 2tt+1
#pragma unroll
                    for (int j = 0; j < 4; ++j)
                        FMA2(acc2[2 * tt + 1][j], A.u[j], o[tt + j]);
            }
            // FMA issue implies all lanes' LDS drained -> elected arrive is safe
            if (lane == 0) mbar_arrive(smem_u32 + MB_EMPTY(s));
            if (++s == NSTAGE) { s = 0; ph ^= 1; }
        }

        // ---- per-tile epilogue (overlaps next tile's producer fills) ----
        const int h = h0 + hl;
#pragma unroll
        for (int dy = 0; dy < CC_ND; ++dy) {
            float f[8];
#pragma unroll
            for (int j = 0; j < 4; ++j)
                UNPACK2(f[2 * j], f[2 * j + 1], acc2[dy][j]);
            float4 r0, r1;
            r0.x = f[0] * inv; r0.y = f[1] * inv; r0.z = f[2] * inv; r0.w = f[3] * inv;
            r1.x = f[4] * inv; r1.y = f[5] * inv; r1.z = f[6] * inv; r1.w = f[7] * inv;
            float* op = &out[(((size_t)(b * CC_NOFF + dxi * CC_ND + dy) * CC_H) + h) * CC_W
                             + CC_PX * wg];
            ((float4*)op)[0] = r0;
            ((float4*)op)[1] = r1;
        }
    }
}

extern "C" void kernel_launch(void* const* d_in, const int* in_sizes, int n_in,
                              void* d_out, int out_size)
{
    const float* x1 = (const float*)d_in[0];
    const float* x2 = (const float*)d_in[1];
    float* out = (float*)d_out;

    cudaFuncSetAttribute(corr_kernel,
                         cudaFuncAttributeMaxDynamicSharedMemorySize, SMEM_BYTES);
    corr_kernel<<<NBLK, NTH, SMEM_BYTES>>>(x1, x2, out);
}